// round 7
// baseline (speedup 1.0000x reference)
#include <cuda_runtime.h>
#include <cstdint>

// Per-slot global accumulators + ticket (zero at module load; last block
// resets -> clean state each launch/graph replay; integer atomics -> exact
// and deterministic).
#define NSLOTS 32
#define SLOT_STRIDE 32   // uints (128B padding)
__device__ unsigned int g_slots[NSLOTS * SLOT_STRIDE];
__device__ unsigned int g_ticket;

__device__ __forceinline__ void accum_lane(float x, float y,
    unsigned int& c0, unsigned int& c1, unsigned int& c2,
    unsigned int& d0, unsigned int& d1, unsigned int& d2,
    unsigned int& i0, unsigned int& i1, unsigned int& i2)
{
    bool m1 = (x == 1.0f), m2 = (x == 2.0f), m3 = (x == 3.0f);
    bool n1 = (y == 1.0f), n2 = (y == 2.0f), n3 = (y == 3.0f);
    c0 += m1; c1 += m2; c2 += m3;
    d0 += n1; d1 += n2; d2 += n3;
    i0 += (m1 & n1); i1 += (m2 & n2); i2 += (m3 & n3);
}

#define BODY(IDX) do {                                            \
    float4 va = __ldcs(&a[(IDX)]);                                \
    float4 vb = __ldcs(&b[(IDX)]);                                \
    accum_lane(va.x, vb.x, c0,c1,c2, d0,d1,d2, i0,i1,i2);         \
    accum_lane(va.y, vb.y, c0,c1,c2, d0,d1,d2, i0,i1,i2);         \
    accum_lane(va.z, vb.z, c0,c1,c2, d0,d1,d2, i0,i1,i2);         \
    accum_lane(va.w, vb.w, c0,c1,c2, d0,d1,d2, i0,i1,i2);         \
} while (0)

__global__ void __launch_bounds__(512) dice_fused_kernel(
    const float4* __restrict__ a, const float4* __restrict__ b,
    int n_vec, float* __restrict__ out)
{
    unsigned int c0 = 0, c1 = 0, c2 = 0;
    unsigned int d0 = 0, d1 = 0, d2 = 0;
    unsigned int i0 = 0, i1 = 0, i2 = 0;

    const int T   = gridDim.x * blockDim.x;
    const int tid = blockIdx.x * blockDim.x + threadIdx.x;

    const int full = n_vec / T;          // iterations every thread does
    const int rem  = n_vec - full * T;   // first `rem` threads do one more

    int idx = tid;
    // Main: unroll-4 over groups with a single check per group; the bulk
    // (full/4 groups) runs check-free inside each group so each group
    // front-batches 8 independent LDG.128.
    int i = 0;
    for (; i + 4 <= full; i += 4) {
        BODY(idx);             idx += T;
        BODY(idx);             idx += T;
        BODY(idx);             idx += T;
        BODY(idx);             idx += T;
    }
    for (; i < full; ++i) { BODY(idx); idx += T; }
    if (tid < rem)         { BODY(idx); }

    // warp reduce 9 counters
    unsigned int v[9] = {c0, c1, c2, d0, d1, d2, i0, i1, i2};
    #pragma unroll
    for (int k = 0; k < 9; ++k) {
        #pragma unroll
        for (int off = 16; off > 0; off >>= 1)
            v[k] += __shfl_down_sync(0xFFFFFFFFu, v[k], off);
    }

    // block reduce via shared atomics
    __shared__ unsigned int s[9];
    __shared__ bool is_last;
    if (threadIdx.x < 9) s[threadIdx.x] = 0u;
    __syncthreads();
    if ((threadIdx.x & 31) == 0) {
        #pragma unroll
        for (int k = 0; k < 9; ++k) atomicAdd(&s[k], v[k]);
    }
    __syncthreads();

    // global accumulate into this block's slot, then ticket
    const unsigned int slot = (blockIdx.x & (NSLOTS - 1)) * SLOT_STRIDE;
    if (threadIdx.x < 9)
        atomicAdd(&g_slots[slot + threadIdx.x], s[threadIdx.x]);
    __threadfence();
    if (threadIdx.x == 0) {
        unsigned int t = atomicAdd(&g_ticket, 1u);
        is_last = (t == gridDim.x - 1u);
    }
    __syncthreads();

    if (is_last) {
        __threadfence();
        __shared__ unsigned int tot_s[9];
        if (threadIdx.x < 9) {
            unsigned int t = 0;
            #pragma unroll
            for (int sl = 0; sl < NSLOTS; ++sl)
                t += g_slots[sl * SLOT_STRIDE + threadIdx.x];
            tot_s[threadIdx.x] = t;
        }
        __syncthreads();

        if (threadIdx.x == 0) {
            const float eps = 1.1920928955078125e-07f;  // np.finfo(float32).eps
            float sum = 0.0f;
            #pragma unroll
            for (int l = 0; l < 3; ++l) {
                float inter = (float)tot_s[6 + l];
                float bot   = (float)tot_s[l] + (float)tot_s[3 + l];
                sum += (2.0f * inter) / (bot + eps);
            }
            out[0] = 1.0f - sum * (1.0f / 3.0f);
        }

        // reset for next launch / graph replay
        for (int k = threadIdx.x; k < NSLOTS * SLOT_STRIDE; k += blockDim.x)
            g_slots[k] = 0u;
        __syncthreads();
        if (threadIdx.x == 0) {
            __threadfence();
            g_ticket = 0u;
        }
    }
}

extern "C" void kernel_launch(void* const* d_in, const int* in_sizes, int n_in,
                              void* d_out, int out_size)
{
    const float4* a = (const float4*)d_in[0];
    const float4* b = (const float4*)d_in[1];
    float* out = (float*)d_out;

    int n = in_sizes[0];        // 512^3, divisible by 4
    int n_vec = n >> 2;

    const int threads = 512;
    const int blocks  = 152 * 4;   // 608: 4 CTA/SM, 2048 thr/SM
    dice_fused_kernel<<<blocks, threads>>>(a, b, n_vec, out);
}

// round 8
// speedup vs baseline: 1.1814x; 1.1814x over previous
#include <cuda_runtime.h>
#include <cstdint>

// Per-slot global accumulators + ticket (zero at module load; last block
// resets -> clean state each launch/graph replay; integer atomics -> exact
// and deterministic).
#define NSLOTS 32
#define SLOT_STRIDE 32   // uints (128B padding)
__device__ unsigned int g_slots[NSLOTS * SLOT_STRIDE];
__device__ unsigned int g_ticket;

__device__ __forceinline__ void accum_lane(float x, float y,
    unsigned int& c0, unsigned int& c1, unsigned int& c2,
    unsigned int& d0, unsigned int& d1, unsigned int& d2,
    unsigned int& i0, unsigned int& i1, unsigned int& i2)
{
    bool m1 = (x == 1.0f), m2 = (x == 2.0f), m3 = (x == 3.0f);
    bool n1 = (y == 1.0f), n2 = (y == 2.0f), n3 = (y == 3.0f);
    c0 += m1; c1 += m2; c2 += m3;
    d0 += n1; d1 += n2; d2 += n3;
    i0 += (m1 & n1); i1 += (m2 & n2); i2 += (m3 & n3);
}

__global__ void __launch_bounds__(256, 8) dice_fused_kernel(
    const float4* __restrict__ a, const float4* __restrict__ b,
    int n_vec, float* __restrict__ out)
{
    unsigned int c0 = 0, c1 = 0, c2 = 0;
    unsigned int d0 = 0, d1 = 0, d2 = 0;
    unsigned int i0 = 0, i1 = 0, i2 = 0;

    const int stride = gridDim.x * blockDim.x;
    int idx = blockIdx.x * blockDim.x + threadIdx.x;

    #pragma unroll 8
    for (; idx < n_vec; idx += stride) {
        float4 va = __ldcs(&a[idx]);
        float4 vb = __ldcs(&b[idx]);
        accum_lane(va.x, vb.x, c0,c1,c2, d0,d1,d2, i0,i1,i2);
        accum_lane(va.y, vb.y, c0,c1,c2, d0,d1,d2, i0,i1,i2);
        accum_lane(va.z, vb.z, c0,c1,c2, d0,d1,d2, i0,i1,i2);
        accum_lane(va.w, vb.w, c0,c1,c2, d0,d1,d2, i0,i1,i2);
    }

    // warp reduce 9 counters
    unsigned int v[9] = {c0, c1, c2, d0, d1, d2, i0, i1, i2};
    #pragma unroll
    for (int k = 0; k < 9; ++k) {
        #pragma unroll
        for (int off = 16; off > 0; off >>= 1)
            v[k] += __shfl_down_sync(0xFFFFFFFFu, v[k], off);
    }

    // block reduce via shared atomics
    __shared__ unsigned int s[9];
    __shared__ bool is_last;
    if (threadIdx.x < 9) s[threadIdx.x] = 0u;
    __syncthreads();
    if ((threadIdx.x & 31) == 0) {
        #pragma unroll
        for (int k = 0; k < 9; ++k) atomicAdd(&s[k], v[k]);
    }
    __syncthreads();

    // global accumulate into this block's slot, then ticket
    const unsigned int slot = (blockIdx.x & (NSLOTS - 1)) * SLOT_STRIDE;
    if (threadIdx.x < 9)
        atomicAdd(&g_slots[slot + threadIdx.x], s[threadIdx.x]);
    __threadfence();
    if (threadIdx.x == 0) {
        unsigned int t = atomicAdd(&g_ticket, 1u);
        is_last = (t == gridDim.x - 1u);
    }
    __syncthreads();

    if (is_last) {
        __threadfence();
        __shared__ unsigned int tot_s[9];
        if (threadIdx.x < 9) {
            unsigned int t = 0;
            #pragma unroll
            for (int sl = 0; sl < NSLOTS; ++sl)
                t += g_slots[sl * SLOT_STRIDE + threadIdx.x];
            tot_s[threadIdx.x] = t;
        }
        __syncthreads();

        if (threadIdx.x == 0) {
            const float eps = 1.1920928955078125e-07f;  // np.finfo(float32).eps
            float sum = 0.0f;
            #pragma unroll
            for (int l = 0; l < 3; ++l) {
                float inter = (float)tot_s[6 + l];
                float bot   = (float)tot_s[l] + (float)tot_s[3 + l];
                sum += (2.0f * inter) / (bot + eps);
            }
            out[0] = 1.0f - sum * (1.0f / 3.0f);
        }

        // reset for next launch / graph replay
        for (int k = threadIdx.x; k < NSLOTS * SLOT_STRIDE; k += blockDim.x)
            g_slots[k] = 0u;
        __syncthreads();
        if (threadIdx.x == 0) {
            __threadfence();
            g_ticket = 0u;
        }
    }
}

extern "C" void kernel_launch(void* const* d_in, const int* in_sizes, int n_in,
                              void* d_out, int out_size)
{
    const float4* a = (const float4*)d_in[0];
    const float4* b = (const float4*)d_in[1];
    float* out = (float*)d_out;

    int n = in_sizes[0];        // 512^3, divisible by 4
    int n_vec = n >> 2;

    const int threads = 256;
    const int blocks  = 152 * 8;   // 1216
    dice_fused_kernel<<<blocks, threads>>>(a, b, n_vec, out);
}